// round 5
// baseline (speedup 1.0000x reference)
#include <cuda_runtime.h>
#include <math.h>
#include <float.h>

#define N 4096
#define IN_F 256
#define H0 64
#define H1 64
#define H2 32
#define CAP 256
#define SLOPE 0.01f
#define WH_BLOCKS 192   // 64 row-tiles x 3 relations

// -------- scratch (device globals; no allocation) --------
__device__ int   g_nbr_idx[3 * N * CAP];
__device__ int   g_nbr_cnt[3 * N];
__device__ float g_Wh[3 * N * H0];
__device__ float g_ssrc[3 * N];
__device__ float g_sdst[3 * N];
__device__ float g_support[N * H1];
__device__ float g_support2[N * H2];
__device__ float g_resid[N * H2];
__device__ float g_Wg1T[H2 * H1];   // Wg1 transposed to [j][k]

__device__ __forceinline__ float leaky(float v) { return v >= 0.f ? v : SLOPE * v; }

// ================= merged kernel 1: wh tiles + adj scan ===================
__device__ void wh_body(int b,
                        const float* __restrict__ x,
                        const float* __restrict__ W1, const float* __restrict__ a1,
                        const float* __restrict__ W2, const float* __restrict__ a2,
                        const float* __restrict__ W3, const float* __restrict__ a3) {
    int r = b >> 6;
    int row0 = (b & 63) * 64;
    const float* W = (r == 0) ? W1 : (r == 1) ? W2 : W3;
    const float* a = (r == 0) ? a1 : (r == 1) ? a2 : a3;
    int tid = threadIdx.x;
    int rg = tid >> 4;
    int cgp = tid & 15;

    __shared__ float sx[64][64];
    __shared__ float sW[64][64];

    float4 acc[4];
#pragma unroll
    for (int q = 0; q < 4; q++) acc[q] = make_float4(0.f, 0.f, 0.f, 0.f);

    for (int k0 = 0; k0 < IN_F; k0 += 64) {
        __syncthreads();
#pragma unroll
        for (int q = 0; q < 4; q++) {
            int lin = tid + q * 256;
            int rr = lin >> 4, c4 = (lin & 15) << 2;
            *(float4*)&sx[rr][c4] = *(const float4*)(x + (size_t)(row0 + rr) * IN_F + k0 + c4);
        }
#pragma unroll
        for (int q = 0; q < 4; q++) {
            int lin = tid + q * 256;
            int kr = lin >> 4, c4 = (lin & 15) << 2;
            *(float4*)&sW[kr][c4] = *(const float4*)(W + (size_t)(k0 + kr) * H0 + c4);
        }
        __syncthreads();
#pragma unroll 16
        for (int kk = 0; kk < 64; kk++) {
            float4 wv = *(float4*)&sW[kk][cgp * 4];
            float xv0 = sx[rg * 4 + 0][kk];
            float xv1 = sx[rg * 4 + 1][kk];
            float xv2 = sx[rg * 4 + 2][kk];
            float xv3 = sx[rg * 4 + 3][kk];
            acc[0].x = fmaf(xv0, wv.x, acc[0].x); acc[0].y = fmaf(xv0, wv.y, acc[0].y);
            acc[0].z = fmaf(xv0, wv.z, acc[0].z); acc[0].w = fmaf(xv0, wv.w, acc[0].w);
            acc[1].x = fmaf(xv1, wv.x, acc[1].x); acc[1].y = fmaf(xv1, wv.y, acc[1].y);
            acc[1].z = fmaf(xv1, wv.z, acc[1].z); acc[1].w = fmaf(xv1, wv.w, acc[1].w);
            acc[2].x = fmaf(xv2, wv.x, acc[2].x); acc[2].y = fmaf(xv2, wv.y, acc[2].y);
            acc[2].z = fmaf(xv2, wv.z, acc[2].z); acc[2].w = fmaf(xv2, wv.w, acc[2].w);
            acc[3].x = fmaf(xv3, wv.x, acc[3].x); acc[3].y = fmaf(xv3, wv.y, acc[3].y);
            acc[3].z = fmaf(xv3, wv.z, acc[3].z); acc[3].w = fmaf(xv3, wv.w, acc[3].w);
        }
    }

    float4 av = *(const float4*)(a + cgp * 4);
    float4 ad = *(const float4*)(a + H0 + cgp * 4);
#pragma unroll
    for (int ri = 0; ri < 4; ri++) {
        int grow = row0 + rg * 4 + ri;
        *(float4*)(g_Wh + ((size_t)r * N + grow) * H0 + cgp * 4) = acc[ri];
        float ps = acc[ri].x * av.x + acc[ri].y * av.y + acc[ri].z * av.z + acc[ri].w * av.w;
        float pd = acc[ri].x * ad.x + acc[ri].y * ad.y + acc[ri].z * ad.z + acc[ri].w * ad.w;
#pragma unroll
        for (int off = 8; off > 0; off >>= 1) {
            ps += __shfl_down_sync(0xffffffffu, ps, off, 16);
            pd += __shfl_down_sync(0xffffffffu, pd, off, 16);
        }
        if (cgp == 0) { g_ssrc[r * N + grow] = ps; g_sdst[r * N + grow] = pd; }
    }
}

__device__ void scan_body(int b, const float* __restrict__ adj) {
    int i = b & (N - 1);
    int r = b >> 12;
    int tid = threadIdx.x;
    int lane = tid & 31, wid = tid >> 5;
    __shared__ int s_wsum[8];

    const float4* row4 = (const float4*)(adj + ((size_t)r * N + i) * N);
    // fully coalesced, streaming (evict-first) loads
    float4 v0 = __ldcs(row4 + tid);
    float4 v1 = __ldcs(row4 + tid + 256);
    float4 v2 = __ldcs(row4 + tid + 512);
    float4 v3 = __ldcs(row4 + tid + 768);
    unsigned mask = 0;
    if (v0.x > 0.f) mask |= 1u << 0;  if (v0.y > 0.f) mask |= 1u << 1;
    if (v0.z > 0.f) mask |= 1u << 2;  if (v0.w > 0.f) mask |= 1u << 3;
    if (v1.x > 0.f) mask |= 1u << 4;  if (v1.y > 0.f) mask |= 1u << 5;
    if (v1.z > 0.f) mask |= 1u << 6;  if (v1.w > 0.f) mask |= 1u << 7;
    if (v2.x > 0.f) mask |= 1u << 8;  if (v2.y > 0.f) mask |= 1u << 9;
    if (v2.z > 0.f) mask |= 1u << 10; if (v2.w > 0.f) mask |= 1u << 11;
    if (v3.x > 0.f) mask |= 1u << 12; if (v3.y > 0.f) mask |= 1u << 13;
    if (v3.z > 0.f) mask |= 1u << 14; if (v3.w > 0.f) mask |= 1u << 15;
    int c = __popc(mask);

    int pre = c;
#pragma unroll
    for (int off = 1; off < 32; off <<= 1) {
        int nv = __shfl_up_sync(0xffffffffu, pre, off);
        if (lane >= off) pre += nv;
    }
    if (lane == 31) s_wsum[wid] = pre;
    __syncthreads();
    int wbase = 0, total = 0;
#pragma unroll
    for (int w = 0; w < 8; w++) {
        int v = s_wsum[w];
        if (w < wid) wbase += v;
        total += v;
    }
    int pos = wbase + pre - c;

    int* gl = g_nbr_idx + ((size_t)(r * N + i)) * CAP;
    unsigned mm = mask;
    while (mm) {
        int bb = __ffs(mm) - 1;
        mm &= mm - 1;
        int q = bb >> 2, j = bb & 3;
        int col = ((tid + (q << 8)) << 2) + j;
        if (pos < CAP) gl[pos] = col;
        pos++;
    }
    if (tid == 0) g_nbr_cnt[r * N + i] = total;
}

__global__ void __launch_bounds__(256)
scan_wh_kernel(const float* __restrict__ x, const float* __restrict__ adj,
               const float* __restrict__ W1, const float* __restrict__ a1,
               const float* __restrict__ W2, const float* __restrict__ a2,
               const float* __restrict__ W3, const float* __restrict__ a3) {
    if (blockIdx.x < WH_BLOCKS)
        wh_body(blockIdx.x, x, W1, a1, W2, a2, W3, a3);
    else
        scan_body(blockIdx.x - WH_BLOCKS, adj);
}

// ==== kernel 2: softmax+gather for 3 relations, fuse, support (2 rows/block)
__global__ void __launch_bounds__(192)
attn_fuse_kernel(const float* __restrict__ Wg0, const float* __restrict__ Wg1) {
    __shared__ float sw[6][CAP];
    __shared__ int   sidx[6][CAP];
    __shared__ float s_hr[6][H0];
    __shared__ float s_hp[2][H0];
    int tid = threadIdx.x;
    int lane = tid & 31, w = tid >> 5;   // warp 0..5

    // one-time Wg1 transpose (block 0 only); consumed by the NEXT kernel
    if (blockIdx.x == 0) {
        for (int t = tid; t < H1 * H2; t += 192) {
            int k = t >> 5, j = t & 31;
            g_Wg1T[j * H1 + k] = Wg1[t];
        }
    }

    {
        int rr = (w >= 3);
        int r = w - 3 * rr;
        int i = blockIdx.x * 2 + rr;
        int id = r * N + i;
        int total = g_nbr_cnt[id];
        int cnt = min(total, CAP);
        const int* gl = g_nbr_idx + (size_t)id * CAP;
        for (int k = lane; k < cnt; k += 32) sidx[w][k] = gl[k];
        __syncwarp();

        // scores + max
        float si = g_ssrc[id];
        float m = -FLT_MAX;
        for (int k = lane; k < cnt; k += 32) {
            float s = leaky(si + g_sdst[r * N + sidx[w][k]]);
            sw[w][k] = s;
            m = fmaxf(m, s);
        }
#pragma unroll
        for (int off = 16; off > 0; off >>= 1)
            m = fmaxf(m, __shfl_xor_sync(0xffffffffu, m, off));

        // exp + sum
        float sum = 0.f;
        for (int k = lane; k < cnt; k += 32) {
            float e = expf(sw[w][k] - m);
            sw[w][k] = e;
            sum += e;
        }
#pragma unroll
        for (int off = 16; off > 0; off >>= 1)
            sum += __shfl_xor_sync(0xffffffffu, sum, off);
        float inv = 1.f / sum;
        __syncwarp();

        // weighted gather of Wh rows; lane owns features (2lane, 2lane+1)
        const float2* Wh2 = (const float2*)g_Wh + (size_t)r * N * 32;
        float2 a0 = {0.f, 0.f}, a1 = {0.f, 0.f}, a2 = {0.f, 0.f}, a3 = {0.f, 0.f};
        int k = 0;
        for (; k + 4 <= cnt; k += 4) {
            int4  jj = *(const int4*)&sidx[w][k];
            float4 ww = *(const float4*)&sw[w][k];
            float2 p0 = Wh2[(size_t)jj.x * 32 + lane];
            float2 p1 = Wh2[(size_t)jj.y * 32 + lane];
            float2 p2 = Wh2[(size_t)jj.z * 32 + lane];
            float2 p3 = Wh2[(size_t)jj.w * 32 + lane];
            a0.x = fmaf(ww.x, p0.x, a0.x); a0.y = fmaf(ww.x, p0.y, a0.y);
            a1.x = fmaf(ww.y, p1.x, a1.x); a1.y = fmaf(ww.y, p1.y, a1.y);
            a2.x = fmaf(ww.z, p2.x, a2.x); a2.y = fmaf(ww.z, p2.y, a2.y);
            a3.x = fmaf(ww.w, p3.x, a3.x); a3.y = fmaf(ww.w, p3.y, a3.y);
        }
        for (; k < cnt; k++) {
            int j = sidx[w][k];
            float wk = sw[w][k];
            float2 p = Wh2[(size_t)j * 32 + lane];
            a0.x = fmaf(wk, p.x, a0.x); a0.y = fmaf(wk, p.y, a0.y);
        }
        float2 o;
        o.x = (a0.x + a1.x + a2.x + a3.x) * inv;
        o.y = (a0.y + a1.y + a2.y + a3.y) * inv;
        *(float2*)&s_hr[w][2 * lane] = o;
    }
    __syncthreads();

    // fuse: sigmoid(mean of 3 relations)
    if (tid < 128) {
        int rr = tid >> 6, f = tid & 63;
        float v = (s_hr[rr * 3 + 0][f] + s_hr[rr * 3 + 1][f] + s_hr[rr * 3 + 2][f]) * (1.f / 3.f);
        s_hp[rr][f] = 1.f / (1.f + expf(-v));
    }
    __syncthreads();

    // support = h' @ Wg0
    if (tid < 128) {
        int rr = tid >> 6, f = tid & 63;
        int i = blockIdx.x * 2 + rr;
        float acc = 0.f;
#pragma unroll 16
        for (int k = 0; k < H0; k++) acc = fmaf(s_hp[rr][k], Wg0[k * H1 + f], acc);
        g_support[(size_t)i * H1 + f] = acc;
    }
}

__device__ __forceinline__ int read_relation(const void* p) {
    int r = *reinterpret_cast<const int*>(p);
    if (r < 0 || r > 2) {
        float fv = *reinterpret_cast<const float*>(p);
        r = (int)fv;
        if (r < 0 || r > 2) r = 0;
    }
    return r;
}

// ================= kernel 3: gnn layer 1 (1 warp/row, no block sync) ======
__global__ void __launch_bounds__(256)
gnn1_kernel(const float* __restrict__ bg0,
            const float* __restrict__ Wr,
            const float* __restrict__ br,
            const void* __restrict__ relation) {
    __shared__ int   sidx[8][CAP];
    __shared__ float shp[8][H1];
    int tid = threadIdx.x;
    int lane = tid & 31, wid = tid >> 5;
    int i = blockIdx.x * 8 + wid;
    int r = read_relation(relation);
    int rowid = r * N + i;
    int total = g_nbr_cnt[rowid];
    int cnt = min(total, CAP);
    const int* gl = g_nbr_idx + (size_t)rowid * CAP;
    for (int k = lane; k < cnt; k += 32) sidx[wid][k] = gl[k];
    __syncwarp();

    // gather: lane owns features (2lane, 2lane+1)
    const float2* sup = (const float2*)g_support;
    float2 a0 = {0.f, 0.f}, a1 = {0.f, 0.f}, a2 = {0.f, 0.f}, a3 = {0.f, 0.f};
    int k = 0;
    for (; k + 4 <= cnt; k += 4) {
        int4 jj = *(const int4*)&sidx[wid][k];
        float2 p0 = sup[(size_t)jj.x * 32 + lane];
        float2 p1 = sup[(size_t)jj.y * 32 + lane];
        float2 p2 = sup[(size_t)jj.z * 32 + lane];
        float2 p3 = sup[(size_t)jj.w * 32 + lane];
        a0.x += p0.x; a0.y += p0.y;
        a1.x += p1.x; a1.y += p1.y;
        a2.x += p2.x; a2.y += p2.y;
        a3.x += p3.x; a3.y += p3.y;
    }
    for (; k < cnt; k++) {
        float2 p = sup[(size_t)sidx[wid][k] * 32 + lane];
        a0.x += p.x; a0.y += p.y;
    }
    float dinv = 1.f / (float)total;
    float2 bg = ((const float2*)bg0)[lane];
    float2 h;
    h.x = leaky((a0.x + a1.x + a2.x + a3.x) * dinv + bg.x);
    h.y = leaky((a0.y + a1.y + a2.y + a3.y) * dinv + bg.y);
    *(float2*)&shp[wid][2 * lane] = h;
    __syncwarp();

    // epilogue: s2[lane] (Wg1T) and resid[lane] (Wr), vectorized over k
    float s2 = 0.f, rr2 = 0.f;
    const float4* wg = (const float4*)(g_Wg1T + lane * H1);
    const float4* wr = (const float4*)(Wr + lane * H1);
    const float4* hp4 = (const float4*)&shp[wid][0];
#pragma unroll
    for (int k4 = 0; k4 < H1 / 4; k4++) {
        float4 hv = hp4[k4];
        float4 g = wg[k4];
        float4 rv = wr[k4];
        s2  = fmaf(hv.x, g.x,  fmaf(hv.y, g.y,  fmaf(hv.z, g.z,  fmaf(hv.w, g.w,  s2))));
        rr2 = fmaf(hv.x, rv.x, fmaf(hv.y, rv.y, fmaf(hv.z, rv.z, fmaf(hv.w, rv.w, rr2))));
    }
    g_support2[(size_t)i * H2 + lane] = s2;
    g_resid[(size_t)i * H2 + lane]    = rr2 + br[lane];
}

// ================= kernel 4: gnn layer 2 + residual -> out ================
__global__ void __launch_bounds__(256)
gnn2_kernel(const float* __restrict__ bg1,
            const void* __restrict__ relation,
            float* __restrict__ out) {
    __shared__ int sidx[8][CAP];
    int tid = threadIdx.x;
    int lane = tid & 31, wid = tid >> 5;
    int i = blockIdx.x * 8 + wid;
    int r = read_relation(relation);
    int rowid = r * N + i;
    int total = g_nbr_cnt[rowid];
    int cnt = min(total, CAP);
    const int* gl = g_nbr_idx + (size_t)rowid * CAP;
    for (int k = lane; k < cnt; k += 32) sidx[wid][k] = gl[k];
    __syncwarp();

    const float* sup2 = g_support2;
    float a0 = 0.f, a1 = 0.f, a2 = 0.f, a3 = 0.f;
    int k = 0;
    for (; k + 4 <= cnt; k += 4) {
        int4 jj = *(const int4*)&sidx[wid][k];
        a0 += sup2[(size_t)jj.x * H2 + lane];
        a1 += sup2[(size_t)jj.y * H2 + lane];
        a2 += sup2[(size_t)jj.z * H2 + lane];
        a3 += sup2[(size_t)jj.w * H2 + lane];
    }
    for (; k < cnt; k++) a0 += sup2[(size_t)sidx[wid][k] * H2 + lane];

    float agg = a0 + a1 + a2 + a3;
    float v = leaky(agg * (1.f / (float)total) + bg1[lane]);
    out[(size_t)i * H2 + lane] = v + g_resid[(size_t)i * H2 + lane];
}

extern "C" void kernel_launch(void* const* d_in, const int* in_sizes, int n_in,
                              void* d_out, int out_size) {
    const float* x   = (const float*)d_in[0];
    const float* adj = (const float*)d_in[1];
    const float* W1  = (const float*)d_in[2];
    const float* a1  = (const float*)d_in[3];
    const float* W2  = (const float*)d_in[4];
    const float* a2  = (const float*)d_in[5];
    const float* W3  = (const float*)d_in[6];
    const float* a3  = (const float*)d_in[7];
    const float* Wg0 = (const float*)d_in[8];
    const float* bg0 = (const float*)d_in[9];
    const float* Wg1 = (const float*)d_in[10];
    const float* bg1 = (const float*)d_in[11];
    const float* Wr  = (const float*)d_in[12];
    const float* br  = (const float*)d_in[13];
    const void*  rel = d_in[14];
    float* out = (float*)d_out;

    scan_wh_kernel<<<WH_BLOCKS + 3 * N, 256>>>(x, adj, W1, a1, W2, a2, W3, a3);
    attn_fuse_kernel<<<N / 2, 192>>>(Wg0, Wg1);
    gnn1_kernel<<<N / 8, 256>>>(bg0, Wr, br, rel);
    gnn2_kernel<<<N / 8, 256>>>(bg1, rel, out);
}